// round 1
// baseline (speedup 1.0000x reference)
#include <cuda_runtime.h>

// Problem constants (shapes are fixed by the dataset)
#define NN 50000
#define EE 800000

// ---------------- device scratch (no allocations allowed) ----------------
__device__ float g_bufT[NN * 128];   // GEMM outputs / GAT "g"
__device__ float g_bufH[NN * 128];   // scatter accumulators
__device__ float g_bufX[NN * 128];   // layer activations
__device__ float g_dinv[NN];
__device__ int   g_deg[NN];
__device__ float g_S[NN * 2];
__device__ float g_Dd[NN * 2];
__device__ float g_MF[NN * 2];
__device__ float g_Z[NN * 2];
__device__ float g_WS[NN * 2];
__device__ unsigned g_MO[NN * 2];
__device__ float g_ebuf[EE * 2];

// ---------------- helpers ----------------
__device__ __forceinline__ float lrelu(float x) { return x > 0.f ? x : 0.2f * x; }

__device__ __forceinline__ unsigned orderf(float f) {
    unsigned u = __float_as_uint(f);
    return (u & 0x80000000u) ? ~u : (u | 0x80000000u);
}
__device__ __forceinline__ float deorderf(unsigned u) {
    return __uint_as_float((u & 0x80000000u) ? (u & 0x7fffffffu) : ~u);
}

// Vectorized no-return global reduction (sm_90+): 1 message per 16 bytes.
__device__ __forceinline__ void red_add_v4(float* a, float4 v) {
    asm volatile("red.global.add.v4.f32 [%0], {%1,%2,%3,%4};"
                 :: "l"(a), "f"(v.x), "f"(v.y), "f"(v.z), "f"(v.w) : "memory");
}

// ---------------- degree / normalization ----------------
__global__ void k_deg_init(int n) {
    int i = blockIdx.x * blockDim.x + threadIdx.x;
    if (i < n) g_deg[i] = 1;   // self loop
}
__global__ void k_deg_count(const int* __restrict__ dst, int e) {
    int i = blockIdx.x * blockDim.x + threadIdx.x;
    if (i < e) atomicAdd(&g_deg[dst[i]], 1);
}
__global__ void k_dinv(int n) {
    int i = blockIdx.x * blockDim.x + threadIdx.x;
    if (i < n) g_dinv[i] = rsqrtf((float)g_deg[i]);
}

__global__ void k_zero(float* __restrict__ p, int count4) {
    int i = blockIdx.x * blockDim.x + threadIdx.x;
    if (i < count4) ((float4*)p)[i] = make_float4(0.f, 0.f, 0.f, 0.f);
}

// ---------------- simple shared-memory GEMM: Y[n,J] = X[n,K] @ W[K,J] ----------------
template <int K, int J, int RPB>
__global__ void k_gemm(const float* __restrict__ X, const float* __restrict__ W,
                       float* __restrict__ Y, int n) {
    __shared__ float Ws[K * J];
    __shared__ float Xs[RPB * K];
    const int nthr = RPB * (J / 4);
    int tid = threadIdx.x;

    for (int i = tid; i < K * J / 4; i += nthr)
        ((float4*)Ws)[i] = ((const float4*)W)[i];

    int row0 = blockIdx.x * RPB;
    for (int i = tid; i < RPB * K / 4; i += nthr) {
        int r = i / (K / 4), c = i % (K / 4);
        int gr = row0 + r;
        ((float4*)Xs)[i] = (gr < n) ? ((const float4*)X)[(size_t)gr * (K / 4) + c]
                                    : make_float4(0.f, 0.f, 0.f, 0.f);
    }
    __syncthreads();

    int r = tid / (J / 4);
    int jt = tid % (J / 4);
    float4 acc = make_float4(0.f, 0.f, 0.f, 0.f);
#pragma unroll
    for (int k = 0; k < K; k++) {
        float xv = Xs[r * K + k];
        float4 w = ((float4*)Ws)[k * (J / 4) + jt];
        acc.x += xv * w.x; acc.y += xv * w.y; acc.z += xv * w.z; acc.w += xv * w.w;
    }
    int gr = row0 + r;
    if (gr < n) ((float4*)Y)[(size_t)gr * (J / 4) + jt] = acc;
}

// ---------------- GCN scatter: H[dst] += dinv[s]*dinv[d] * T[src]  (64 ch, 16 lanes/edge) ----------------
__global__ void k_gcn_scatter(const int* __restrict__ src, const int* __restrict__ dst,
                              const float* __restrict__ T, float* __restrict__ H, int e) {
    int g = blockIdx.x * blockDim.x + threadIdx.x;
    int edge = g >> 4, lane = g & 15;
    if (edge >= e) return;
    int s = src[edge], d = dst[edge];
    float coef = g_dinv[s] * g_dinv[d];
    float4 v = ((const float4*)T)[(size_t)s * 16 + lane];
    v.x *= coef; v.y *= coef; v.z *= coef; v.w *= coef;
    red_add_v4(&H[(size_t)d * 64 + lane * 4], v);
}

// finish GCN: X = relu(H + dinv^2 * T (self loop) + b)
__global__ void k_gcn_finish(const float* __restrict__ T, const float* __restrict__ H,
                             const float* __restrict__ b, float* __restrict__ X, int n) {
    int idx = blockIdx.x * blockDim.x + threadIdx.x;
    if (idx >= n * 64) return;
    int v = idx >> 6, c = idx & 63;
    float di = g_dinv[v];
    float val = H[idx] + di * di * T[idx] + b[c];
    X[idx] = fmaxf(val, 0.f);
}

// ---------------- GAT ----------------
// per (node, head): s = <g, a_src>, d = <g, a_dst>
__global__ void k_sd(const float* __restrict__ G, const float* __restrict__ asrc,
                     const float* __restrict__ adst, int n2, int ch) {
    int vh = blockIdx.x * blockDim.x + threadIdx.x;
    if (vh >= n2) return;
    int h = vh & 1;
    int f4 = ch / 4;
    const float4* row = (const float4*)G + (size_t)vh * f4;
    const float4* as = (const float4*)asrc + h * f4;
    const float4* ad = (const float4*)adst + h * f4;
    float s = 0.f, d = 0.f;
    for (int i = 0; i < f4; i++) {
        float4 g = row[i], a = as[i], b = ad[i];
        s += g.x * a.x + g.y * a.y + g.z * a.z + g.w * a.w;
        d += g.x * b.x + g.y * b.y + g.z * b.z + g.w * b.w;
    }
    g_S[vh] = s; g_Dd[vh] = d;
}

__global__ void k_m_init(int n2) {
    int vh = blockIdx.x * blockDim.x + threadIdx.x;
    if (vh >= n2) return;
    g_MO[vh] = orderf(lrelu(g_S[vh] + g_Dd[vh]));   // self loop score
}
__global__ void k_m_edge(const int* __restrict__ src, const int* __restrict__ dst, int e) {
    int i = blockIdx.x * blockDim.x + threadIdx.x;
    if (i >= e * 2) return;
    int edge = i >> 1, h = i & 1;
    int s = src[edge], d = dst[edge];
    float sc = lrelu(g_S[s * 2 + h] + g_Dd[d * 2 + h]);
    atomicMax(&g_MO[d * 2 + h], orderf(sc));
}
__global__ void k_z_init(int n2) {
    int vh = blockIdx.x * blockDim.x + threadIdx.x;
    if (vh >= n2) return;
    float mf = deorderf(g_MO[vh]);
    g_MF[vh] = mf;
    g_Z[vh] = __expf(lrelu(g_S[vh] + g_Dd[vh]) - mf);   // self loop term
}
__global__ void k_z_edge(const int* __restrict__ src, const int* __restrict__ dst, int e) {
    int i = blockIdx.x * blockDim.x + threadIdx.x;
    if (i >= e * 2) return;
    int edge = i >> 1, h = i & 1;
    int s = src[edge], d = dst[edge];
    float sc = lrelu(g_S[s * 2 + h] + g_Dd[d * 2 + h]);
    float a = __expf(sc - g_MF[d * 2 + h]);
    g_ebuf[i] = a;
    atomicAdd(&g_Z[d * 2 + h], a);
}
__global__ void k_wself(int n2) {
    int vh = blockIdx.x * blockDim.x + threadIdx.x;
    if (vh >= n2) return;
    g_WS[vh] = __expf(lrelu(g_S[vh] + g_Dd[vh]) - g_MF[vh]) / (g_Z[vh] + 1e-16f);
}
// H = w_self * G   (full overwrite => no memset needed)
__global__ void k_self_init(const float* __restrict__ G, float* __restrict__ H,
                            int count4, int chf4) {
    int i = blockIdx.x * blockDim.x + threadIdx.x;
    if (i >= count4) return;
    int vh = i / chf4;
    float w = g_WS[vh];
    float4 g = ((const float4*)G)[i];
    g.x *= w; g.y *= w; g.z *= w; g.w *= w;
    ((float4*)H)[i] = g;
}
// weighted scatter: F4 float4 lanes per edge (heads*ch/4); h = lane/(F4/2)
template <int F4>
__global__ void k_gat_scatter(const int* __restrict__ src, const int* __restrict__ dst,
                              const float* __restrict__ G, float* __restrict__ H, int e) {
    int g = blockIdx.x * blockDim.x + threadIdx.x;
    int edge = g / F4, lane = g % F4;
    if (edge >= e) return;
    int s = src[edge], d = dst[edge];
    int h = lane / (F4 / 2);
    float w = g_ebuf[edge * 2 + h] / (g_Z[d * 2 + h] + 1e-16f);
    float4 v = ((const float4*)G)[(size_t)s * F4 + lane];
    v.x *= w; v.y *= w; v.z *= w; v.w *= w;
    red_add_v4(&H[((size_t)d * F4 + lane) * 4], v);
}

__global__ void k_gat1_finish(const float* __restrict__ H, const float* __restrict__ bg,
                              float* __restrict__ X, int n) {
    int idx = blockIdx.x * blockDim.x + threadIdx.x;
    if (idx >= n * 128) return;
    X[idx] = fmaxf(H[idx] + bg[idx & 127], 0.f);
}

// final: mean over 2 heads (32 ch) + bias, then log_softmax; one warp per node
__global__ void k_out_final(const float* __restrict__ H, const float* __restrict__ bg2,
                            float* __restrict__ out, int n) {
    int t = blockIdx.x * blockDim.x + threadIdx.x;
    int node = t >> 5, c = t & 31;
    if (node >= n) return;
    float v = 0.5f * (H[(size_t)node * 64 + c] + H[(size_t)node * 64 + 32 + c]) + bg2[c];
    float mx = v;
#pragma unroll
    for (int o = 16; o; o >>= 1) mx = fmaxf(mx, __shfl_xor_sync(0xffffffffu, mx, o));
    float ex = __expf(v - mx);
    float sum = ex;
#pragma unroll
    for (int o = 16; o; o >>= 1) sum += __shfl_xor_sync(0xffffffffu, sum, o);
    out[(size_t)node * 32 + c] = v - mx - logf(sum);
}

// ---------------- launcher ----------------
static inline int cdiv(long long a, int b) { return (int)((a + b - 1) / b); }

extern "C" void kernel_launch(void* const* d_in, const int* in_sizes, int n_in,
                              void* d_out, int out_size) {
    const float* x   = (const float*)d_in[0];
    const int*   ei  = (const int*)d_in[1];
    const float* W1  = (const float*)d_in[2];
    const float* b1  = (const float*)d_in[3];
    const float* W2  = (const float*)d_in[4];
    const float* b2  = (const float*)d_in[5];
    const float* Wg1 = (const float*)d_in[6];
    const float* as1 = (const float*)d_in[7];
    const float* ad1 = (const float*)d_in[8];
    const float* bg1 = (const float*)d_in[9];
    const float* Wg2 = (const float*)d_in[10];
    const float* as2 = (const float*)d_in[11];
    const float* ad2 = (const float*)d_in[12];
    const float* bg2 = (const float*)d_in[13];

    int n = in_sizes[0] / 128;
    int e = in_sizes[1] / 2;
    const int* src = ei;
    const int* dst = ei + e;

    float* T = nullptr; cudaGetSymbolAddress((void**)&T, g_bufT);
    float* H = nullptr; cudaGetSymbolAddress((void**)&H, g_bufH);
    float* X = nullptr; cudaGetSymbolAddress((void**)&X, g_bufX);
    float* out = (float*)d_out;

    const int B = 256;

    // degrees / norm
    k_deg_init<<<cdiv(n, B), B>>>(n);
    k_deg_count<<<cdiv(e, B), B>>>(dst, e);
    k_dinv<<<cdiv(n, B), B>>>(n);

    // -------- GCN1: x[ N,128 ] @ W1 -> 64 --------
    k_gemm<128, 64, 16><<<cdiv(n, 16), 256>>>(x, W1, T, n);
    k_zero<<<cdiv((long long)n * 16, B), B>>>(H, n * 16);
    k_gcn_scatter<<<cdiv((long long)e * 16, B), B>>>(src, dst, T, H, e);
    k_gcn_finish<<<cdiv((long long)n * 64, B), B>>>(T, H, b1, X, n);

    // -------- GCN2: 64 -> 64 --------
    k_gemm<64, 64, 16><<<cdiv(n, 16), 256>>>(X, W2, T, n);
    k_zero<<<cdiv((long long)n * 16, B), B>>>(H, n * 16);
    k_gcn_scatter<<<cdiv((long long)e * 16, B), B>>>(src, dst, T, H, e);
    k_gcn_finish<<<cdiv((long long)n * 64, B), B>>>(T, H, b2, X, n);

    // -------- GAT1: 64 -> (2 heads x 64), concat --------
    k_gemm<64, 128, 8><<<cdiv(n, 8), 256>>>(X, Wg1, T, n);
    k_sd<<<cdiv((long long)n * 2, B), B>>>(T, as1, ad1, n * 2, 64);
    k_m_init<<<cdiv((long long)n * 2, B), B>>>(n * 2);
    k_m_edge<<<cdiv((long long)e * 2, B), B>>>(src, dst, e);
    k_z_init<<<cdiv((long long)n * 2, B), B>>>(n * 2);
    k_z_edge<<<cdiv((long long)e * 2, B), B>>>(src, dst, e);
    k_wself<<<cdiv((long long)n * 2, B), B>>>(n * 2);
    k_self_init<<<cdiv((long long)n * 32, B), B>>>(T, H, n * 32, 16);
    k_gat_scatter<32><<<cdiv((long long)e * 32, B), B>>>(src, dst, T, H, e);
    k_gat1_finish<<<cdiv((long long)n * 128, B), B>>>(H, bg1, X, n);

    // -------- GAT2: 128 -> (2 heads x 32), mean --------
    k_gemm<128, 64, 16><<<cdiv(n, 16), 256>>>(X, Wg2, T, n);
    k_sd<<<cdiv((long long)n * 2, B), B>>>(T, as2, ad2, n * 2, 32);
    k_m_init<<<cdiv((long long)n * 2, B), B>>>(n * 2);
    k_m_edge<<<cdiv((long long)e * 2, B), B>>>(src, dst, e);
    k_z_init<<<cdiv((long long)n * 2, B), B>>>(n * 2);
    k_z_edge<<<cdiv((long long)e * 2, B), B>>>(src, dst, e);
    k_wself<<<cdiv((long long)n * 2, B), B>>>(n * 2);
    k_self_init<<<cdiv((long long)n * 16, B), B>>>(T, H, n * 16, 8);
    k_gat_scatter<16><<<cdiv((long long)e * 16, B), B>>>(src, dst, T, H, e);
    k_out_final<<<cdiv((long long)n * 32, B), B>>>(H, bg2, out, n);
}

// round 2
// speedup vs baseline: 1.5674x; 1.5674x over previous
#include <cuda_runtime.h>

#define NN 50000
#define EE 800000
#define FULL 0xffffffffu

// ---------------- device scratch ----------------
__device__ float g_bufT[NN * 128];   // GEMM outputs (messages)
__device__ float g_bufX[NN * 128];   // layer activations
__device__ float g_dinv[NN];
__device__ int   g_cnt[NN];
__device__ int   g_off[NN + 1];
__device__ int   g_cur[NN];
__device__ int   g_es[EE];           // CSR: src ids sorted by dst
__device__ float2 g_Sv[NN];          // per-node per-head <g, a_src>
__device__ float2 g_Dv[NN];          // per-node per-head <g, a_dst>

// ---------------- helpers ----------------
__device__ __forceinline__ float lrelu(float x) { return x > 0.f ? x : 0.2f * x; }

// ---------------- CSR build ----------------
__global__ void k_cnt_zero(int n) {
    int i = blockIdx.x * blockDim.x + threadIdx.x;
    if (i < n) g_cnt[i] = 0;
}
__global__ void k_hist(const int* __restrict__ dst, int e) {
    int i = blockIdx.x * blockDim.x + threadIdx.x;
    if (i < e) atomicAdd(&g_cnt[dst[i]], 1);
}
__global__ void k_scan(int n, int e) {
    __shared__ int ps[1024];
    int tid = threadIdx.x;
    int chunk = (n + 1023) >> 10;
    int b = tid * chunk, en = min(n, b + chunk);
    int s = 0;
    for (int i = b; i < en; i++) s += g_cnt[i];
    ps[tid] = s;
    __syncthreads();
    for (int o = 1; o < 1024; o <<= 1) {
        int v = (tid >= o) ? ps[tid - o] : 0;
        __syncthreads();
        ps[tid] += v;
        __syncthreads();
    }
    int run = tid ? ps[tid - 1] : 0;
    for (int i = b; i < en; i++) {
        g_off[i] = run; g_cur[i] = run;
        run += g_cnt[i];
    }
    if (tid == 0) g_off[n] = e;
}
__global__ void k_fill(const int* __restrict__ src, const int* __restrict__ dst, int e) {
    int i = blockIdx.x * blockDim.x + threadIdx.x;
    if (i >= e) return;
    int d = dst[i];
    int p = atomicAdd(&g_cur[d], 1);
    g_es[p] = src[i];
}
__global__ void k_dinv(int n) {
    int i = blockIdx.x * blockDim.x + threadIdx.x;
    if (i < n) g_dinv[i] = rsqrtf((float)(g_cnt[i] + 1));
}

// ---------------- register-tiled GEMM: Y[n,J] = X[n,K] @ W[K,J] ----------------
// 64 rows/block, 256 threads, each thread 4 rows x (J/16) cols.
template <int K, int J>
__global__ __launch_bounds__(256)
void k_gemm(const float* __restrict__ X, const float* __restrict__ W,
            float* __restrict__ Y, int n) {
    __shared__ float Ws[K * J];      // [k][j]
    __shared__ float Xs[32 * 64];    // transposed chunk [kk][row]
    const int JT = J / 64;           // 1 or 2
    int tid = threadIdx.x;
    int tx = tid & 15, ty = tid >> 4;
    int row0 = blockIdx.x * 64;

    for (int i = tid; i < K * J / 4; i += 256)
        ((float4*)Ws)[i] = ((const float4*)W)[i];

    float acc[JT][4][4];
#pragma unroll
    for (int jc = 0; jc < JT; jc++)
#pragma unroll
        for (int i = 0; i < 4; i++)
#pragma unroll
            for (int c = 0; c < 4; c++) acc[jc][i][c] = 0.f;

    for (int k0 = 0; k0 < K; k0 += 32) {
        __syncthreads();
        // load 64 rows x 32 k's of X, transposed into Xs[kk][row]
        for (int i = tid; i < 64 * 8; i += 256) {
            int r = i >> 3, c4 = i & 7;
            int gr = row0 + r;
            float4 v = make_float4(0.f, 0.f, 0.f, 0.f);
            if (gr < n) v = ((const float4*)X)[(size_t)gr * (K / 4) + (k0 >> 2) + c4];
            int kk = c4 * 4;
            Xs[(kk + 0) * 64 + r] = v.x;
            Xs[(kk + 1) * 64 + r] = v.y;
            Xs[(kk + 2) * 64 + r] = v.z;
            Xs[(kk + 3) * 64 + r] = v.w;
        }
        __syncthreads();
#pragma unroll
        for (int kk = 0; kk < 32; kk++) {
            float xr[4];
            *(float4*)xr = *(const float4*)(Xs + kk * 64 + ty * 4);
#pragma unroll
            for (int jc = 0; jc < JT; jc++) {
                float wr[4];
                *(float4*)wr = *(const float4*)(Ws + (k0 + kk) * J + jc * 64 + tx * 4);
#pragma unroll
                for (int i = 0; i < 4; i++)
#pragma unroll
                    for (int c = 0; c < 4; c++) acc[jc][i][c] += xr[i] * wr[c];
            }
        }
    }
#pragma unroll
    for (int i = 0; i < 4; i++) {
        int gr = row0 + ty * 4 + i;
        if (gr >= n) continue;
#pragma unroll
        for (int jc = 0; jc < JT; jc++) {
            float4 v = make_float4(acc[jc][i][0], acc[jc][i][1], acc[jc][i][2], acc[jc][i][3]);
            ((float4*)Y)[(size_t)gr * (J / 4) + jc * 16 + tx] = v;
        }
    }
}

// ---------------- GCN: warp per node, gather + register accumulate ----------------
__global__ void k_gcn_node(const float* __restrict__ T, const float* __restrict__ b,
                           float* __restrict__ X, int n) {
    int w = (blockIdx.x * blockDim.x + threadIdx.x) >> 5;
    int lane = threadIdx.x & 31;
    if (w >= n) return;
    float dd = g_dinv[w];
    const float2* T2 = (const float2*)T;
    float2 self = T2[(size_t)w * 32 + lane];
    float2 acc;
    acc.x = dd * dd * self.x;
    acc.y = dd * dd * self.y;
    int beg = g_off[w], end = g_off[w + 1];
    for (int base = beg; base < end; base += 32) {
        int j = base + lane;
        int sj = w; float cj = 0.f;
        if (j < end) { sj = g_es[j]; cj = g_dinv[sj]; }
        int cnt = min(32, end - base);
        for (int t = 0; t < cnt; t++) {
            int s = __shfl_sync(FULL, sj, t);
            float coef = __shfl_sync(FULL, cj, t) * dd;
            float2 v = T2[(size_t)s * 32 + lane];
            acc.x += coef * v.x;
            acc.y += coef * v.y;
        }
    }
    float2 bb = ((const float2*)b)[lane];
    float2 o;
    o.x = fmaxf(acc.x + bb.x, 0.f);
    o.y = fmaxf(acc.y + bb.y, 0.f);
    ((float2*)X)[(size_t)w * 32 + lane] = o;
}

// ---------------- GAT score precompute: per (node,head) dot products ----------------
template <int CH>
__global__ void k_sd(const float* __restrict__ G, const float* __restrict__ asrc,
                     const float* __restrict__ adst, int n2) {
    int vh = blockIdx.x * blockDim.x + threadIdx.x;
    if (vh >= n2) return;
    int h = vh & 1;
    const int f4 = CH / 4;
    const float4* row = (const float4*)G + (size_t)vh * f4;
    const float4* as = (const float4*)asrc + h * f4;
    const float4* ad = (const float4*)adst + h * f4;
    float s = 0.f, d = 0.f;
#pragma unroll
    for (int i = 0; i < f4; i++) {
        float4 g = row[i], a = as[i], bb = ad[i];
        s += g.x * a.x + g.y * a.y + g.z * a.z + g.w * a.w;
        d += g.x * bb.x + g.y * bb.y + g.z * bb.z + g.w * bb.w;
    }
    ((float*)g_Sv)[vh] = s;
    ((float*)g_Dv)[vh] = d;
}

// ---------------- fused GAT layer: warp per node ----------------
// CH = per-head channels. CONCAT: write relu(concat)+bias to X; else mean heads,
// +bias, log_softmax, write to out.
template <int CH, bool CONCAT>
__global__ void k_gat_node(const float* __restrict__ T, const float* __restrict__ bias,
                           float* __restrict__ X, float* __restrict__ out, int n) {
    int w = (blockIdx.x * blockDim.x + threadIdx.x) >> 5;
    int lane = threadIdx.x & 31;
    if (w >= n) return;
    float2 Dd = g_Dv[w];
    float2 Sw = g_Sv[w];
    float self0 = lrelu(Sw.x + Dd.x);
    float self1 = lrelu(Sw.y + Dd.y);
    int beg = g_off[w], end = g_off[w + 1];

    // --- max over incoming edges (incl self loop) ---
    float m0 = self0, m1 = self1;
    for (int j = beg + lane; j < end; j += 32) {
        float2 sv = g_Sv[g_es[j]];
        m0 = fmaxf(m0, lrelu(sv.x + Dd.x));
        m1 = fmaxf(m1, lrelu(sv.y + Dd.y));
    }
#pragma unroll
    for (int o = 16; o; o >>= 1) {
        m0 = fmaxf(m0, __shfl_xor_sync(FULL, m0, o));
        m1 = fmaxf(m1, __shfl_xor_sync(FULL, m1, o));
    }
    // --- sum of exp ---
    float z0 = (lane == 0) ? __expf(self0 - m0) : 0.f;
    float z1 = (lane == 0) ? __expf(self1 - m1) : 0.f;
    for (int j = beg + lane; j < end; j += 32) {
        float2 sv = g_Sv[g_es[j]];
        z0 += __expf(lrelu(sv.x + Dd.x) - m0);
        z1 += __expf(lrelu(sv.y + Dd.y) - m1);
    }
#pragma unroll
    for (int o = 16; o; o >>= 1) {
        z0 += __shfl_xor_sync(FULL, z0, o);
        z1 += __shfl_xor_sync(FULL, z1, o);
    }
    float iz0 = 1.f / (z0 + 1e-16f);
    float iz1 = 1.f / (z1 + 1e-16f);

    // --- weighted feature accumulate ---
    constexpr int VEC = (CH == 64) ? 4 : 2;   // floats per lane (F = 2*CH)
    float acc[VEC];
    float wself = (lane < 16) ? __expf(self0 - m0) * iz0 : __expf(self1 - m1) * iz1;
    if (CH == 64) {
        float4 v = ((const float4*)T)[(size_t)w * 32 + lane];
        acc[0] = wself * v.x; acc[1] = wself * v.y;
        acc[2] = wself * v.z; acc[3] = wself * v.w;
    } else {
        float2 v = ((const float2*)T)[(size_t)w * 32 + lane];
        acc[0] = wself * v.x; acc[1] = wself * v.y;
    }
    for (int base = beg; base < end; base += 32) {
        int j = base + lane;
        int sj = w; float a0 = 0.f, a1 = 0.f;
        if (j < end) {
            sj = g_es[j];
            float2 sv = g_Sv[sj];
            a0 = __expf(lrelu(sv.x + Dd.x) - m0) * iz0;
            a1 = __expf(lrelu(sv.y + Dd.y) - m1) * iz1;
        }
        int cnt = min(32, end - base);
        for (int t = 0; t < cnt; t++) {
            int s = __shfl_sync(FULL, sj, t);
            float wa = __shfl_sync(FULL, a0, t);
            float wb = __shfl_sync(FULL, a1, t);
            float wgt = (lane < 16) ? wa : wb;
            if (CH == 64) {
                float4 v = ((const float4*)T)[(size_t)s * 32 + lane];
                acc[0] += wgt * v.x; acc[1] += wgt * v.y;
                acc[2] += wgt * v.z; acc[3] += wgt * v.w;
            } else {
                float2 v = ((const float2*)T)[(size_t)s * 32 + lane];
                acc[0] += wgt * v.x; acc[1] += wgt * v.y;
            }
        }
    }

    if (CONCAT) {
        float4 bb = ((const float4*)bias)[lane];
        float4 o;
        o.x = fmaxf(acc[0] + bb.x, 0.f);
        o.y = fmaxf(acc[1] + bb.y, 0.f);
        o.z = fmaxf(acc[2] + bb.z, 0.f);
        o.w = fmaxf(acc[3] + bb.w, 0.f);
        ((float4*)X)[(size_t)w * 32 + lane] = o;
    } else {
        // lane holds flat channels {2*lane, 2*lane+1} of F=64 (head = lane>=16).
        // out channel c: head0 value at lane c/2 comp c&1; head1 at lane 16+c/2.
        float x0 = __shfl_sync(FULL, acc[0], lane >> 1);
        float x1 = __shfl_sync(FULL, acc[1], lane >> 1);
        float h0 = (lane & 1) ? x1 : x0;
        float y0 = __shfl_sync(FULL, acc[0], 16 + (lane >> 1));
        float y1 = __shfl_sync(FULL, acc[1], 16 + (lane >> 1));
        float h1 = (lane & 1) ? y1 : y0;
        float v = 0.5f * (h0 + h1) + bias[lane];
        float mx = v;
#pragma unroll
        for (int o = 16; o; o >>= 1) mx = fmaxf(mx, __shfl_xor_sync(FULL, mx, o));
        float ex = __expf(v - mx);
        float sum = ex;
#pragma unroll
        for (int o = 16; o; o >>= 1) sum += __shfl_xor_sync(FULL, sum, o);
        out[(size_t)w * 32 + lane] = v - mx - logf(sum);
    }
}

// ---------------- launcher ----------------
static inline int cdiv(long long a, int b) { return (int)((a + b - 1) / b); }

extern "C" void kernel_launch(void* const* d_in, const int* in_sizes, int n_in,
                              void* d_out, int out_size) {
    const float* x   = (const float*)d_in[0];
    const int*   ei  = (const int*)d_in[1];
    const float* W1  = (const float*)d_in[2];
    const float* b1  = (const float*)d_in[3];
    const float* W2  = (const float*)d_in[4];
    const float* b2  = (const float*)d_in[5];
    const float* Wg1 = (const float*)d_in[6];
    const float* as1 = (const float*)d_in[7];
    const float* ad1 = (const float*)d_in[8];
    const float* bg1 = (const float*)d_in[9];
    const float* Wg2 = (const float*)d_in[10];
    const float* as2 = (const float*)d_in[11];
    const float* ad2 = (const float*)d_in[12];
    const float* bg2 = (const float*)d_in[13];

    int n = in_sizes[0] / 128;
    int e = in_sizes[1] / 2;
    const int* src = ei;
    const int* dst = ei + e;

    float* T = nullptr; cudaGetSymbolAddress((void**)&T, g_bufT);
    float* X = nullptr; cudaGetSymbolAddress((void**)&X, g_bufX);
    float* out = (float*)d_out;

    const int B = 256;
    int nwarp_blocks = cdiv((long long)n * 32, B);

    // --- CSR build + degrees ---
    k_cnt_zero<<<cdiv(n, B), B>>>(n);
    k_hist<<<cdiv(e, B), B>>>(dst, e);
    k_scan<<<1, 1024>>>(n, e);
    k_fill<<<cdiv(e, B), B>>>(src, dst, e);
    k_dinv<<<cdiv(n, B), B>>>(n);

    // --- GCN1: 128 -> 64 ---
    k_gemm<128, 64><<<cdiv(n, 64), 256>>>(x, W1, T, n);
    k_gcn_node<<<nwarp_blocks, B>>>(T, b1, X, n);

    // --- GCN2: 64 -> 64 ---
    k_gemm<64, 64><<<cdiv(n, 64), 256>>>(X, W2, T, n);
    k_gcn_node<<<nwarp_blocks, B>>>(T, b2, X, n);

    // --- GAT1: 64 -> 2x64 concat ---
    k_gemm<64, 128><<<cdiv(n, 64), 256>>>(X, Wg1, T, n);
    k_sd<64><<<cdiv((long long)n * 2, B), B>>>(T, as1, ad1, n * 2);
    k_gat_node<64, true><<<nwarp_blocks, B>>>(T, bg1, X, nullptr, n);

    // --- GAT2: 128 -> 2x32 mean + log_softmax ---
    k_gemm<128, 64><<<cdiv(n, 64), 256>>>(X, Wg2, T, n);
    k_sd<32><<<cdiv((long long)n * 2, B), B>>>(T, as2, ad2, n * 2);
    k_gat_node<32, false><<<nwarp_blocks, B>>>(T, bg2, nullptr, out, n);
}

// round 3
// speedup vs baseline: 1.5774x; 1.0064x over previous
#include <cuda_runtime.h>

#define NN 50000
#define EE 800000
#define FULL 0xffffffffu

// ---------------- device scratch ----------------
__device__ float g_bufT[NN * 128];   // GEMM outputs (messages)
__device__ float g_bufX[NN * 128];   // layer activations
__device__ float g_dinv[NN];
__device__ int   g_cnt[NN];
__device__ int   g_off[NN + 1];
__device__ int   g_cur[NN];
__device__ int   g_es[EE];           // CSR: src ids sorted by dst
__device__ float2 g_Sv[NN];          // per-node per-head <g, a_src>
__device__ float2 g_Dv[NN];          // per-node per-head <g, a_dst>
__device__ float2 g_eb[EE];          // cached per-edge raw scores (2 heads)

// ---------------- helpers ----------------
__device__ __forceinline__ float lrelu(float x) { return x > 0.f ? x : 0.2f * x; }

// ---------------- CSR build ----------------
__global__ void k_cnt_zero(int n) {
    int i = blockIdx.x * blockDim.x + threadIdx.x;
    if (i < n) g_cnt[i] = 0;
}
__global__ void k_hist(const int* __restrict__ dst, int e) {
    int i = blockIdx.x * blockDim.x + threadIdx.x;
    if (i < e) atomicAdd(&g_cnt[dst[i]], 1);
}
__global__ void k_scan(int n, int e) {
    __shared__ int ps[1024];
    int tid = threadIdx.x;
    int chunk = (n + 1023) >> 10;
    int b = tid * chunk, en = min(n, b + chunk);
    int s = 0;
    for (int i = b; i < en; i++) s += g_cnt[i];
    ps[tid] = s;
    __syncthreads();
    for (int o = 1; o < 1024; o <<= 1) {
        int v = (tid >= o) ? ps[tid - o] : 0;
        __syncthreads();
        ps[tid] += v;
        __syncthreads();
    }
    int run = tid ? ps[tid - 1] : 0;
    for (int i = b; i < en; i++) {
        g_off[i] = run; g_cur[i] = run;
        run += g_cnt[i];
    }
    if (tid == 0) g_off[n] = e;
}
__global__ void k_fill(const int* __restrict__ src, const int* __restrict__ dst, int e) {
    int i = blockIdx.x * blockDim.x + threadIdx.x;
    if (i >= e) return;
    int d = dst[i];
    int p = atomicAdd(&g_cur[d], 1);
    g_es[p] = src[i];
}
__global__ void k_dinv(int n) {
    int i = blockIdx.x * blockDim.x + threadIdx.x;
    if (i < n) g_dinv[i] = rsqrtf((float)(g_cnt[i] + 1));
}

// ---------------- register-tiled GEMM: Y[n,J] = X[n,K] @ W[K,J] ----------------
template <int K, int J>
__global__ __launch_bounds__(256)
void k_gemm(const float* __restrict__ X, const float* __restrict__ W,
            float* __restrict__ Y, int n) {
    __shared__ float Ws[K * J];
    __shared__ float Xs[32 * 64];
    const int JT = J / 64;
    int tid = threadIdx.x;
    int tx = tid & 15, ty = tid >> 4;
    int row0 = blockIdx.x * 64;

    for (int i = tid; i < K * J / 4; i += 256)
        ((float4*)Ws)[i] = ((const float4*)W)[i];

    float acc[JT][4][4];
#pragma unroll
    for (int jc = 0; jc < JT; jc++)
#pragma unroll
        for (int i = 0; i < 4; i++)
#pragma unroll
            for (int c = 0; c < 4; c++) acc[jc][i][c] = 0.f;

    for (int k0 = 0; k0 < K; k0 += 32) {
        __syncthreads();
        for (int i = tid; i < 64 * 8; i += 256) {
            int r = i >> 3, c4 = i & 7;
            int gr = row0 + r;
            float4 v = make_float4(0.f, 0.f, 0.f, 0.f);
            if (gr < n) v = ((const float4*)X)[(size_t)gr * (K / 4) + (k0 >> 2) + c4];
            int kk = c4 * 4;
            Xs[(kk + 0) * 64 + r] = v.x;
            Xs[(kk + 1) * 64 + r] = v.y;
            Xs[(kk + 2) * 64 + r] = v.z;
            Xs[(kk + 3) * 64 + r] = v.w;
        }
        __syncthreads();
#pragma unroll
        for (int kk = 0; kk < 32; kk++) {
            float xr[4];
            *(float4*)xr = *(const float4*)(Xs + kk * 64 + ty * 4);
#pragma unroll
            for (int jc = 0; jc < JT; jc++) {
                float wr[4];
                *(float4*)wr = *(const float4*)(Ws + (k0 + kk) * J + jc * 64 + tx * 4);
#pragma unroll
                for (int i = 0; i < 4; i++)
#pragma unroll
                    for (int c = 0; c < 4; c++) acc[jc][i][c] += xr[i] * wr[c];
            }
        }
    }
#pragma unroll
    for (int i = 0; i < 4; i++) {
        int gr = row0 + ty * 4 + i;
        if (gr >= n) continue;
#pragma unroll
        for (int jc = 0; jc < JT; jc++) {
            float4 v = make_float4(acc[jc][i][0], acc[jc][i][1], acc[jc][i][2], acc[jc][i][3]);
            ((float4*)Y)[(size_t)gr * (J / 4) + jc * 16 + tx] = v;
        }
    }
}

// ---------------- GCN: HALF-warp per node, float4 gather, unroll-4 ----------------
__global__ void k_gcn_node(const float* __restrict__ T, const float* __restrict__ b,
                           float* __restrict__ X, int n) {
    int g = blockIdx.x * blockDim.x + threadIdx.x;
    int w = g >> 4;                 // node
    int lane = threadIdx.x & 15;    // lane in half-warp
    if (w >= n) return;
    float dd = g_dinv[w];
    const float4* T4 = (const float4*)T;
    float4 self = T4[(size_t)w * 16 + lane];
    float ax = dd * dd * self.x, ay = dd * dd * self.y;
    float az = dd * dd * self.z, aw = dd * dd * self.w;
    int beg = g_off[w], end = g_off[w + 1];
    for (int base = beg; base < end; base += 16) {
        int j = base + lane;
        int sj = w; float cj = 0.f;
        if (j < end) { sj = g_es[j]; cj = g_dinv[sj] * dd; }
        int cnt4 = (min(16, end - base) + 3) & ~3;
        for (int t = 0; t < cnt4; t += 4) {
#pragma unroll
            for (int u = 0; u < 4; u++) {
                int s = __shfl_sync(FULL, sj, t + u, 16);
                float c = __shfl_sync(FULL, cj, t + u, 16);
                float4 v = T4[(size_t)s * 16 + lane];
                ax += c * v.x; ay += c * v.y; az += c * v.z; aw += c * v.w;
            }
        }
    }
    float4 bb = ((const float4*)b)[lane];
    float4 o;
    o.x = fmaxf(ax + bb.x, 0.f);
    o.y = fmaxf(ay + bb.y, 0.f);
    o.z = fmaxf(az + bb.z, 0.f);
    o.w = fmaxf(aw + bb.w, 0.f);
    ((float4*)X)[(size_t)w * 16 + lane] = o;
}

// ---------------- GAT score precompute ----------------
template <int CH>
__global__ void k_sd(const float* __restrict__ G, const float* __restrict__ asrc,
                     const float* __restrict__ adst, int n2) {
    int vh = blockIdx.x * blockDim.x + threadIdx.x;
    if (vh >= n2) return;
    int h = vh & 1;
    const int f4 = CH / 4;
    const float4* row = (const float4*)G + (size_t)vh * f4;
    const float4* as = (const float4*)asrc + h * f4;
    const float4* ad = (const float4*)adst + h * f4;
    float s = 0.f, d = 0.f;
#pragma unroll
    for (int i = 0; i < f4; i++) {
        float4 g = row[i], a = as[i], bb = ad[i];
        s += g.x * a.x + g.y * a.y + g.z * a.z + g.w * a.w;
        d += g.x * bb.x + g.y * bb.y + g.z * bb.z + g.w * bb.w;
    }
    ((float*)g_Sv)[vh] = s;
    ((float*)g_Dv)[vh] = d;
}

// ---------------- fused GAT layer: warp per node, online softmax + cached scores ----
template <int CH, bool CONCAT>
__global__ void k_gat_node(const float* __restrict__ T, const float* __restrict__ bias,
                           float* __restrict__ X, float* __restrict__ out, int n) {
    int w = (blockIdx.x * blockDim.x + threadIdx.x) >> 5;
    int lane = threadIdx.x & 31;
    if (w >= n) return;
    float2 Dd = g_Dv[w];
    float2 Sw = g_Sv[w];
    float self0 = lrelu(Sw.x + Dd.x);
    float self1 = lrelu(Sw.y + Dd.y);
    int beg = g_off[w], end = g_off[w + 1];

    // --- pass 1: online max+sum, cache raw scores sequentially ---
    float m0 = (lane == 0) ? self0 : -1e30f;
    float m1 = (lane == 0) ? self1 : -1e30f;
    float z0 = (lane == 0) ? 1.f : 0.f;
    float z1 = (lane == 0) ? 1.f : 0.f;
    for (int j = beg + lane; j < end; j += 32) {
        float2 sv = g_Sv[g_es[j]];
        float e0 = lrelu(sv.x + Dd.x);
        float e1 = lrelu(sv.y + Dd.y);
        g_eb[j] = make_float2(e0, e1);
        if (e0 > m0) { z0 = z0 * __expf(m0 - e0) + 1.f; m0 = e0; }
        else           z0 += __expf(e0 - m0);
        if (e1 > m1) { z1 = z1 * __expf(m1 - e1) + 1.f; m1 = e1; }
        else           z1 += __expf(e1 - m1);
    }
#pragma unroll
    for (int o = 16; o; o >>= 1) {
        float om = __shfl_xor_sync(FULL, m0, o);
        float oz = __shfl_xor_sync(FULL, z0, o);
        float M = fmaxf(m0, om);
        z0 = z0 * __expf(m0 - M) + oz * __expf(om - M);
        m0 = M;
        om = __shfl_xor_sync(FULL, m1, o);
        oz = __shfl_xor_sync(FULL, z1, o);
        M = fmaxf(m1, om);
        z1 = z1 * __expf(m1 - M) + oz * __expf(om - M);
        m1 = M;
    }
    float iz0 = 1.f / (z0 + 1e-16f);
    float iz1 = 1.f / (z1 + 1e-16f);

    // --- pass 2: weighted feature accumulate (scores re-read sequentially) ---
    constexpr int VEC = (CH == 64) ? 4 : 2;
    float acc[VEC];
    float wself = (lane < 16) ? __expf(self0 - m0) * iz0 : __expf(self1 - m1) * iz1;
    if (CH == 64) {
        float4 v = ((const float4*)T)[(size_t)w * 32 + lane];
        acc[0] = wself * v.x; acc[1] = wself * v.y;
        acc[2] = wself * v.z; acc[3] = wself * v.w;
    } else {
        float2 v = ((const float2*)T)[(size_t)w * 32 + lane];
        acc[0] = wself * v.x; acc[1] = wself * v.y;
    }
    for (int base = beg; base < end; base += 32) {
        int j = base + lane;
        int sj = w; float a0 = 0.f, a1 = 0.f;
        if (j < end) {
            sj = g_es[j];
            float2 eb = g_eb[j];
            a0 = __expf(eb.x - m0) * iz0;
            a1 = __expf(eb.y - m1) * iz1;
        }
        int cnt4 = (min(32, end - base) + 3) & ~3;
        for (int t = 0; t < cnt4; t += 4) {
#pragma unroll
            for (int u = 0; u < 4; u++) {
                int s = __shfl_sync(FULL, sj, t + u);
                float wa = __shfl_sync(FULL, a0, t + u);
                float wb = __shfl_sync(FULL, a1, t + u);
                float wgt = (lane < 16) ? wa : wb;
                if (CH == 64) {
                    float4 v = ((const float4*)T)[(size_t)s * 32 + lane];
                    acc[0] += wgt * v.x; acc[1] += wgt * v.y;
                    acc[2] += wgt * v.z; acc[3] += wgt * v.w;
                } else {
                    float2 v = ((const float2*)T)[(size_t)s * 32 + lane];
                    acc[0] += wgt * v.x; acc[1] += wgt * v.y;
                }
            }
        }
    }

    if (CONCAT) {
        float4 bb = ((const float4*)bias)[lane];
        float4 o;
        o.x = fmaxf(acc[0] + bb.x, 0.f);
        o.y = fmaxf(acc[1] + bb.y, 0.f);
        o.z = fmaxf(acc[2] + bb.z, 0.f);
        o.w = fmaxf(acc[3] + bb.w, 0.f);
        ((float4*)X)[(size_t)w * 32 + lane] = o;
    } else {
        float x0 = __shfl_sync(FULL, acc[0], lane >> 1);
        float x1 = __shfl_sync(FULL, acc[1], lane >> 1);
        float h0 = (lane & 1) ? x1 : x0;
        float y0 = __shfl_sync(FULL, acc[0], 16 + (lane >> 1));
        float y1 = __shfl_sync(FULL, acc[1], 16 + (lane >> 1));
        float h1 = (lane & 1) ? y1 : y0;
        float v = 0.5f * (h0 + h1) + bias[lane];
        float mx = v;
#pragma unroll
        for (int o = 16; o; o >>= 1) mx = fmaxf(mx, __shfl_xor_sync(FULL, mx, o));
        float ex = __expf(v - mx);
        float sum = ex;
#pragma unroll
        for (int o = 16; o; o >>= 1) sum += __shfl_xor_sync(FULL, sum, o);
        out[(size_t)w * 32 + lane] = v - mx - logf(sum);
    }
}

// ---------------- launcher ----------------
static inline int cdiv(long long a, int b) { return (int)((a + b - 1) / b); }

extern "C" void kernel_launch(void* const* d_in, const int* in_sizes, int n_in,
                              void* d_out, int out_size) {
    const float* x   = (const float*)d_in[0];
    const int*   ei  = (const int*)d_in[1];
    const float* W1  = (const float*)d_in[2];
    const float* b1  = (const float*)d_in[3];
    const float* W2  = (const float*)d_in[4];
    const float* b2  = (const float*)d_in[5];
    const float* Wg1 = (const float*)d_in[6];
    const float* as1 = (const float*)d_in[7];
    const float* ad1 = (const float*)d_in[8];
    const float* bg1 = (const float*)d_in[9];
    const float* Wg2 = (const float*)d_in[10];
    const float* as2 = (const float*)d_in[11];
    const float* ad2 = (const float*)d_in[12];
    const float* bg2 = (const float*)d_in[13];

    int n = in_sizes[0] / 128;
    int e = in_sizes[1] / 2;
    const int* src = ei;
    const int* dst = ei + e;

    float* T = nullptr; cudaGetSymbolAddress((void**)&T, g_bufT);
    float* X = nullptr; cudaGetSymbolAddress((void**)&X, g_bufX);
    float* out = (float*)d_out;

    const int B = 256;
    int half_blocks = cdiv((long long)n * 16, B);
    int warp_blocks = cdiv((long long)n * 32, B);

    // --- CSR build + degrees ---
    k_cnt_zero<<<cdiv(n, B), B>>>(n);
    k_hist<<<cdiv(e, B), B>>>(dst, e);
    k_scan<<<1, 1024>>>(n, e);
    k_fill<<<cdiv(e, B), B>>>(src, dst, e);
    k_dinv<<<cdiv(n, B), B>>>(n);

    // --- GCN1: 128 -> 64 ---
    k_gemm<128, 64><<<cdiv(n, 64), 256>>>(x, W1, T, n);
    k_gcn_node<<<half_blocks, B>>>(T, b1, X, n);

    // --- GCN2: 64 -> 64 ---
    k_gemm<64, 64><<<cdiv(n, 64), 256>>>(X, W2, T, n);
    k_gcn_node<<<half_blocks, B>>>(T, b2, X, n);

    // --- GAT1: 64 -> 2x64 concat ---
    k_gemm<64, 128><<<cdiv(n, 64), 256>>>(X, Wg1, T, n);
    k_sd<64><<<cdiv((long long)n * 2, B), B>>>(T, as1, ad1, n * 2);
    k_gat_node<64, true><<<warp_blocks, B>>>(T, bg1, X, nullptr, n);

    // --- GAT2: 128 -> 2x32 mean + log_softmax ---
    k_gemm<128, 64><<<cdiv(n, 64), 256>>>(X, Wg2, T, n);
    k_sd<32><<<cdiv((long long)n * 2, B), B>>>(T, as2, ad2, n * 2);
    k_gat_node<32, false><<<warp_blocks, B>>>(T, bg2, nullptr, out, n);
}

// round 4
// speedup vs baseline: 2.2489x; 1.4257x over previous
#include <cuda_runtime.h>

#define NN 50000
#define EE 800000
#define FULL 0xffffffffu

// ---------------- device scratch ----------------
__device__ float g_bufT[NN * 128];   // GEMM outputs (messages)
__device__ float g_bufX[NN * 128];   // layer activations
__device__ float g_dinv[NN];
__device__ int   g_cnt[NN];
__device__ int   g_off[NN];
__device__ int   g_cur[NN];
__device__ int   g_tot;
__device__ int   g_es[EE];           // CSR: src ids grouped by dst
__device__ float2 g_Sv[NN];          // per-node per-head <g, a_src>
__device__ float2 g_Dv[NN];          // per-node per-head <g, a_dst>
__device__ float2 g_eb[EE];          // cached per-edge raw scores (2 heads)

// ---------------- helpers ----------------
__device__ __forceinline__ float lrelu(float x) { return x > 0.f ? x : 0.2f * x; }

// ---------------- CSR build ----------------
__global__ void k_cnt_zero(int n) {
    int i = blockIdx.x * blockDim.x + threadIdx.x;
    if (i == 0) g_tot = 0;
    if (i < n) g_cnt[i] = 0;
}
__global__ void k_hist(const int* __restrict__ dst, int e) {
    int i = blockIdx.x * blockDim.x + threadIdx.x;
    if (i < e) atomicAdd(&g_cnt[dst[i]], 1);
}
// segment allocation in arbitrary order: off via atomic cursor; also dinv
__global__ void k_off(int n) {
    int i = blockIdx.x * blockDim.x + threadIdx.x;
    if (i >= n) return;
    int c = g_cnt[i];
    int p = atomicAdd(&g_tot, c);
    g_off[i] = p;
    g_cur[i] = p;
    g_dinv[i] = rsqrtf((float)(c + 1));
}
__global__ void k_fill(const int* __restrict__ src, const int* __restrict__ dst, int e) {
    int i = blockIdx.x * blockDim.x + threadIdx.x;
    if (i >= e) return;
    int d = dst[i];
    int p = atomicAdd(&g_cur[d], 1);
    g_es[p] = src[i];
}

// ---------------- register-tiled GEMM: Y[n,J] = X[n,K] @ W[K,J] ----------------
// 128 rows/block, 256 threads (16x16), each thread 8 rows x 4*(J/64) cols.
// SD=1: also emit GAT score dots for CH=64/J=128; SD=2: CH=32/J=64.
template <int K, int J, int SD>
__global__ __launch_bounds__(256)
void k_gemm(const float* __restrict__ X, const float* __restrict__ W,
            float* __restrict__ Y, const float* __restrict__ asv,
            const float* __restrict__ adv, int n) {
    __shared__ float Ws[K * J];
    __shared__ float Xs[32 * 128];
    const int JT = J / 64;
    int tid = threadIdx.x;
    int tx = tid & 15, ty = tid >> 4;
    int row0 = blockIdx.x * 128;

    for (int i = tid; i < K * J / 4; i += 256)
        ((float4*)Ws)[i] = ((const float4*)W)[i];

    float acc[JT][8][4];
#pragma unroll
    for (int jc = 0; jc < JT; jc++)
#pragma unroll
        for (int i = 0; i < 8; i++)
#pragma unroll
            for (int c = 0; c < 4; c++) acc[jc][i][c] = 0.f;

    for (int k0 = 0; k0 < K; k0 += 32) {
        __syncthreads();
        // load 128 rows x 32 k's of X, transposed into Xs[kk][row]
#pragma unroll
        for (int it = 0; it < 4; it++) {
            int i = tid + it * 256;
            int r = i >> 3, c4 = i & 7;
            int gr = row0 + r;
            float4 v = make_float4(0.f, 0.f, 0.f, 0.f);
            if (gr < n) v = ((const float4*)X)[(size_t)gr * (K / 4) + (k0 >> 2) + c4];
            int kk = c4 * 4;
            Xs[(kk + 0) * 128 + r] = v.x;
            Xs[(kk + 1) * 128 + r] = v.y;
            Xs[(kk + 2) * 128 + r] = v.z;
            Xs[(kk + 3) * 128 + r] = v.w;
        }
        __syncthreads();
#pragma unroll
        for (int kk = 0; kk < 32; kk++) {
            float xr[8];
            *(float4*)xr = *(const float4*)(Xs + kk * 128 + ty * 8);
            *(float4*)(xr + 4) = *(const float4*)(Xs + kk * 128 + ty * 8 + 4);
#pragma unroll
            for (int jc = 0; jc < JT; jc++) {
                float wr[4];
                *(float4*)wr = *(const float4*)(Ws + (k0 + kk) * J + jc * 64 + tx * 4);
#pragma unroll
                for (int i = 0; i < 8; i++)
#pragma unroll
                    for (int c = 0; c < 4; c++) acc[jc][i][c] += xr[i] * wr[c];
            }
        }
    }
#pragma unroll
    for (int i = 0; i < 8; i++) {
        int gr = row0 + ty * 8 + i;
        if (gr >= n) continue;
#pragma unroll
        for (int jc = 0; jc < JT; jc++) {
            float4 v = make_float4(acc[jc][i][0], acc[jc][i][1], acc[jc][i][2], acc[jc][i][3]);
            ((float4*)Y)[(size_t)gr * (J / 4) + jc * 16 + tx] = v;
        }
    }

    if (SD == 1) {
        // J=128, heads = jc; per-row dot with asv/adv, reduce over 16 tx lanes
        float as[2][4], ad[2][4];
#pragma unroll
        for (int jc = 0; jc < JT; jc++)
#pragma unroll
            for (int c = 0; c < 4; c++) {
                as[jc][c] = asv[jc * 64 + tx * 4 + c];
                ad[jc][c] = adv[jc * 64 + tx * 4 + c];
            }
#pragma unroll
        for (int i = 0; i < 8; i++) {
            float s0 = 0.f, d0 = 0.f, s1 = 0.f, d1 = 0.f;
#pragma unroll
            for (int c = 0; c < 4; c++) {
                s0 += acc[0][i][c] * as[0][c];
                d0 += acc[0][i][c] * ad[0][c];
                s1 += acc[JT - 1][i][c] * as[1][c];
                d1 += acc[JT - 1][i][c] * ad[1][c];
            }
#pragma unroll
            for (int o = 8; o; o >>= 1) {
                s0 += __shfl_xor_sync(FULL, s0, o);
                d0 += __shfl_xor_sync(FULL, d0, o);
                s1 += __shfl_xor_sync(FULL, s1, o);
                d1 += __shfl_xor_sync(FULL, d1, o);
            }
            int gr = row0 + ty * 8 + i;
            if (tx == 0 && gr < n) {
                g_Sv[gr] = make_float2(s0, s1);
                g_Dv[gr] = make_float2(d0, d1);
            }
        }
    } else if (SD == 2) {
        // J=64, head = tx>>3 (cols 0-31 head0, 32-63 head1); reduce over 8 lanes
        float as[4], ad[4];
        int h = tx >> 3;
#pragma unroll
        for (int c = 0; c < 4; c++) {
            as[c] = asv[h * 32 + (tx & 7) * 4 + c];
            ad[c] = adv[h * 32 + (tx & 7) * 4 + c];
        }
#pragma unroll
        for (int i = 0; i < 8; i++) {
            float s = 0.f, d = 0.f;
#pragma unroll
            for (int c = 0; c < 4; c++) {
                s += acc[0][i][c] * as[c];
                d += acc[0][i][c] * ad[c];
            }
#pragma unroll
            for (int o = 4; o; o >>= 1) {
                s += __shfl_xor_sync(FULL, s, o);
                d += __shfl_xor_sync(FULL, d, o);
            }
            int gr = row0 + ty * 8 + i;
            if ((tx & 7) == 0 && gr < n) {
                ((float*)g_Sv)[gr * 2 + h] = s;
                ((float*)g_Dv)[gr * 2 + h] = d;
            }
        }
    }
}

// ---------------- GCN: HALF-warp per node, float4 gather ----------------
__global__ void k_gcn_node(const float* __restrict__ T, const float* __restrict__ b,
                           float* __restrict__ X, int n) {
    int g = blockIdx.x * blockDim.x + threadIdx.x;
    int w = g >> 4;
    int lane = threadIdx.x & 15;
    if (w >= n) return;
    float dd = g_dinv[w];
    const float4* T4 = (const float4*)T;
    float4 self = T4[(size_t)w * 16 + lane];
    float ax = dd * dd * self.x, ay = dd * dd * self.y;
    float az = dd * dd * self.z, aw = dd * dd * self.w;
    int beg = g_off[w], end = beg + g_cnt[w];
    for (int base = beg; base < end; base += 16) {
        int j = base + lane;
        int sj = w; float cj = 0.f;
        if (j < end) { sj = g_es[j]; cj = g_dinv[sj] * dd; }
        int cnt4 = (min(16, end - base) + 3) & ~3;
        for (int t = 0; t < cnt4; t += 4) {
#pragma unroll
            for (int u = 0; u < 4; u++) {
                int s = __shfl_sync(FULL, sj, t + u, 16);
                float c = __shfl_sync(FULL, cj, t + u, 16);
                float4 v = T4[(size_t)s * 16 + lane];
                ax += c * v.x; ay += c * v.y; az += c * v.z; aw += c * v.w;
            }
        }
    }
    float4 bb = ((const float4*)b)[lane];
    float4 o;
    o.x = fmaxf(ax + bb.x, 0.f);
    o.y = fmaxf(ay + bb.y, 0.f);
    o.z = fmaxf(az + bb.z, 0.f);
    o.w = fmaxf(aw + bb.w, 0.f);
    ((float4*)X)[(size_t)w * 16 + lane] = o;
}

// ---------------- fused GAT layer: warp per node, online softmax + cached scores ----
template <int CH, bool CONCAT>
__global__ void k_gat_node(const float* __restrict__ T, const float* __restrict__ bias,
                           float* __restrict__ X, float* __restrict__ out, int n) {
    int w = (blockIdx.x * blockDim.x + threadIdx.x) >> 5;
    int lane = threadIdx.x & 31;
    if (w >= n) return;
    float2 Dd = g_Dv[w];
    float2 Sw = g_Sv[w];
    float self0 = lrelu(Sw.x + Dd.x);
    float self1 = lrelu(Sw.y + Dd.y);
    int beg = g_off[w], end = beg + g_cnt[w];

    // --- pass 1: online max+sum, cache raw scores sequentially ---
    float m0 = (lane == 0) ? self0 : -1e30f;
    float m1 = (lane == 0) ? self1 : -1e30f;
    float z0 = (lane == 0) ? 1.f : 0.f;
    float z1 = (lane == 0) ? 1.f : 0.f;
    for (int j = beg + lane; j < end; j += 32) {
        float2 sv = g_Sv[g_es[j]];
        float e0 = lrelu(sv.x + Dd.x);
        float e1 = lrelu(sv.y + Dd.y);
        g_eb[j] = make_float2(e0, e1);
        if (e0 > m0) { z0 = z0 * __expf(m0 - e0) + 1.f; m0 = e0; }
        else           z0 += __expf(e0 - m0);
        if (e1 > m1) { z1 = z1 * __expf(m1 - e1) + 1.f; m1 = e1; }
        else           z1 += __expf(e1 - m1);
    }
#pragma unroll
    for (int o = 16; o; o >>= 1) {
        float om = __shfl_xor_sync(FULL, m0, o);
        float oz = __shfl_xor_sync(FULL, z0, o);
        float M = fmaxf(m0, om);
        z0 = z0 * __expf(m0 - M) + oz * __expf(om - M);
        m0 = M;
        om = __shfl_xor_sync(FULL, m1, o);
        oz = __shfl_xor_sync(FULL, z1, o);
        M = fmaxf(m1, om);
        z1 = z1 * __expf(m1 - M) + oz * __expf(om - M);
        m1 = M;
    }
    float iz0 = 1.f / (z0 + 1e-16f);
    float iz1 = 1.f / (z1 + 1e-16f);

    // --- pass 2: weighted feature accumulate ---
    constexpr int VEC = (CH == 64) ? 4 : 2;
    float acc[VEC];
    float wself = (lane < 16) ? __expf(self0 - m0) * iz0 : __expf(self1 - m1) * iz1;
    if (CH == 64) {
        float4 v = ((const float4*)T)[(size_t)w * 32 + lane];
        acc[0] = wself * v.x; acc[1] = wself * v.y;
        acc[2] = wself * v.z; acc[3] = wself * v.w;
    } else {
        float2 v = ((const float2*)T)[(size_t)w * 32 + lane];
        acc[0] = wself * v.x; acc[1] = wself * v.y;
    }
    for (int base = beg; base < end; base += 32) {
        int j = base + lane;
        int sj = w; float a0 = 0.f, a1 = 0.f;
        if (j < end) {
            sj = g_es[j];
            float2 eb = g_eb[j];
            a0 = __expf(eb.x - m0) * iz0;
            a1 = __expf(eb.y - m1) * iz1;
        }
        int cnt4 = (min(32, end - base) + 3) & ~3;
        for (int t = 0; t < cnt4; t += 4) {
#pragma unroll
            for (int u = 0; u < 4; u++) {
                int s = __shfl_sync(FULL, sj, t + u);
                float wa = __shfl_sync(FULL, a0, t + u);
                float wb = __shfl_sync(FULL, a1, t + u);
                float wgt = (lane < 16) ? wa : wb;
                if (CH == 64) {
                    float4 v = ((const float4*)T)[(size_t)s * 32 + lane];
                    acc[0] += wgt * v.x; acc[1] += wgt * v.y;
                    acc[2] += wgt * v.z; acc[3] += wgt * v.w;
                } else {
                    float2 v = ((const float2*)T)[(size_t)s * 32 + lane];
                    acc[0] += wgt * v.x; acc[1] += wgt * v.y;
                }
            }
        }
    }

    if (CONCAT) {
        float4 bb = ((const float4*)bias)[lane];
        float4 o;
        o.x = fmaxf(acc[0] + bb.x, 0.f);
        o.y = fmaxf(acc[1] + bb.y, 0.f);
        o.z = fmaxf(acc[2] + bb.z, 0.f);
        o.w = fmaxf(acc[3] + bb.w, 0.f);
        ((float4*)X)[(size_t)w * 32 + lane] = o;
    } else {
        float x0 = __shfl_sync(FULL, acc[0], lane >> 1);
        float x1 = __shfl_sync(FULL, acc[1], lane >> 1);
        float h0 = (lane & 1) ? x1 : x0;
        float y0 = __shfl_sync(FULL, acc[0], 16 + (lane >> 1));
        float y1 = __shfl_sync(FULL, acc[1], 16 + (lane >> 1));
        float h1 = (lane & 1) ? y1 : y0;
        float v = 0.5f * (h0 + h1) + bias[lane];
        float mx = v;
#pragma unroll
        for (int o = 16; o; o >>= 1) mx = fmaxf(mx, __shfl_xor_sync(FULL, mx, o));
        float ex = __expf(v - mx);
        float sum = ex;
#pragma unroll
        for (int o = 16; o; o >>= 1) sum += __shfl_xor_sync(FULL, sum, o);
        out[(size_t)w * 32 + lane] = v - mx - logf(sum);
    }
}

// ---------------- launcher ----------------
static inline int cdiv(long long a, int b) { return (int)((a + b - 1) / b); }

extern "C" void kernel_launch(void* const* d_in, const int* in_sizes, int n_in,
                              void* d_out, int out_size) {
    const float* x   = (const float*)d_in[0];
    const int*   ei  = (const int*)d_in[1];
    const float* W1  = (const float*)d_in[2];
    const float* b1  = (const float*)d_in[3];
    const float* W2  = (const float*)d_in[4];
    const float* b2  = (const float*)d_in[5];
    const float* Wg1 = (const float*)d_in[6];
    const float* as1 = (const float*)d_in[7];
    const float* ad1 = (const float*)d_in[8];
    const float* bg1 = (const float*)d_in[9];
    const float* Wg2 = (const float*)d_in[10];
    const float* as2 = (const float*)d_in[11];
    const float* ad2 = (const float*)d_in[12];
    const float* bg2 = (const float*)d_in[13];

    int n = in_sizes[0] / 128;
    int e = in_sizes[1] / 2;
    const int* src = ei;
    const int* dst = ei + e;

    float* T = nullptr; cudaGetSymbolAddress((void**)&T, g_bufT);
    float* X = nullptr; cudaGetSymbolAddress((void**)&X, g_bufX);
    float* out = (float*)d_out;

    static cudaStream_t s1 = nullptr;
    static cudaEvent_t e0 = nullptr, e1 = nullptr;
    if (!s1) {
        cudaStreamCreateWithFlags(&s1, cudaStreamNonBlocking);
        cudaEventCreateWithFlags(&e0, cudaEventDisableTiming);
        cudaEventCreateWithFlags(&e1, cudaEventDisableTiming);
    }

    const int B = 256;
    int half_blocks = cdiv((long long)n * 16, B);
    int warp_blocks = cdiv((long long)n * 32, B);
    int gemm_blocks = cdiv(n, 128);

    // --- fork: CSR build on side stream, GEMM1 on main stream ---
    cudaEventRecord(e0, 0);
    cudaStreamWaitEvent(s1, e0, 0);
    k_cnt_zero<<<cdiv(n, B), B, 0, s1>>>(n);
    k_hist<<<cdiv(e, B), B, 0, s1>>>(dst, e);
    k_off<<<cdiv(n, B), B, 0, s1>>>(n);
    k_fill<<<cdiv(e, B), B, 0, s1>>>(src, dst, e);
    cudaEventRecord(e1, s1);

    // --- GCN1: 128 -> 64 ---
    k_gemm<128, 64, 0><<<gemm_blocks, 256>>>(x, W1, T, nullptr, nullptr, n);
    cudaStreamWaitEvent(0, e1, 0);   // join CSR before aggregation
    k_gcn_node<<<half_blocks, B>>>(T, b1, X, n);

    // --- GCN2: 64 -> 64 ---
    k_gemm<64, 64, 0><<<gemm_blocks, 256>>>(X, W2, T, nullptr, nullptr, n);
    k_gcn_node<<<half_blocks, B>>>(T, b2, X, n);

    // --- GAT1: 64 -> 2x64 concat (scores fused into GEMM epilogue) ---
    k_gemm<64, 128, 1><<<gemm_blocks, 256>>>(X, Wg1, T, as1, ad1, n);
    k_gat_node<64, true><<<warp_blocks, B>>>(T, bg1, X, nullptr, n);

    // --- GAT2: 128 -> 2x32 mean + log_softmax ---
    k_gemm<128, 64, 2><<<gemm_blocks, 256>>>(X, Wg2, T, as2, ad2, n);
    k_gat_node<32, false><<<warp_blocks, B>>>(T, bg2, nullptr, out, n);
}